// round 1
// baseline (speedup 1.0000x reference)
#include <cuda_runtime.h>
#include <math.h>

#define NMAX 200000
#define DFEAT 256
#define MNB   64
#define KSEL  3

// Scratch (allocation-free): per-node projections.
__device__ float g_s_self[NMAX];
__device__ float g_s_all[NMAX];

// ---------------------------------------------------------------------------
// Kernel 1: one warp per node. s_self = x·wa + b, s_all = x·wb.
// Each lane reads 2 float4 (coalesced 512B chunks per warp step), dual FMA
// chains, single combined shfl reduction.
// ---------------------------------------------------------------------------
__global__ void __launch_bounds__(256) score_kernel(const float* __restrict__ x,
                                                    const float* __restrict__ W,
                                                    const float* __restrict__ bias,
                                                    int N) {
    int warp = (blockIdx.x * 256 + threadIdx.x) >> 5;
    int lane = threadIdx.x & 31;
    if (warp >= N) return;

    const float4* xr = (const float4*)(x + (size_t)warp * DFEAT);
    const float4* wa = (const float4*)(W);          // W[0:256]
    const float4* wb = (const float4*)(W + DFEAT);  // W[256:512]

    float sa = 0.f, sb = 0.f;
#pragma unroll
    for (int k = 0; k < 2; k++) {
        int i = lane + 32 * k;            // 0..63 float4 per row
        float4 xv = __ldg(xr + i);
        float4 av = __ldg(wa + i);
        float4 bv = __ldg(wb + i);
        sa = fmaf(xv.x, av.x, sa); sa = fmaf(xv.y, av.y, sa);
        sa = fmaf(xv.z, av.z, sa); sa = fmaf(xv.w, av.w, sa);
        sb = fmaf(xv.x, bv.x, sb); sb = fmaf(xv.y, bv.y, sb);
        sb = fmaf(xv.z, bv.z, sb); sb = fmaf(xv.w, bv.w, sb);
    }
#pragma unroll
    for (int off = 16; off; off >>= 1) {
        sa += __shfl_xor_sync(0xffffffffu, sa, off);
        sb += __shfl_xor_sync(0xffffffffu, sb, off);
    }
    if (lane == 0) {
        g_s_self[warp] = sa + bias[0];
        g_s_all[warp]  = sb;
    }
}

// Order-preserving float<->uint mapping (total order on floats incl. -inf).
__device__ __forceinline__ unsigned fkey(float f) {
    unsigned u = __float_as_uint(f);
    return (u & 0x80000000u) ? ~u : (u | 0x80000000u);
}
__device__ __forceinline__ float funkey(unsigned u) {
    unsigned b = (u & 0x80000000u) ? (u & 0x7fffffffu) : ~u;
    return __uint_as_float(b);
}

// ---------------------------------------------------------------------------
// Kernel 2: one warp per node. Gather 64 neighbor scores (L2-resident s_all),
// score = exp(leaky_relu(s_self + s_nb)), masked by count, then 3 passes of
// warp-argmax on 64-bit keys. Key = (score_bits << 6) | (63 - pos) so equal
// scores break ties toward the LOWER position index — matching jax top_k.
// ---------------------------------------------------------------------------
__global__ void __launch_bounds__(256) topk_kernel(const int* __restrict__ neighbors,
                                                   const int* __restrict__ counts,
                                                   float* __restrict__ out,
                                                   int N) {
    int node = (blockIdx.x * 256 + threadIdx.x) >> 5;
    int lane = threadIdx.x & 31;
    if (node >= N) return;

    int   cnt = counts[node];
    float ss  = g_s_self[node];

    const int2* nb = (const int2*)(neighbors + (size_t)node * MNB);
    int2 jj = __ldg(nb + lane);            // positions 2*lane, 2*lane+1
    int p0 = 2 * lane, p1 = 2 * lane + 1;

    float s0 = -INFINITY, s1 = -INFINITY;
    if (p0 < cnt) {
        float t = ss + g_s_all[jj.x];
        t = (t >= 0.f) ? t : 0.01f * t;    // leaky_relu, jax default slope
        s0 = expf(t);
    }
    if (p1 < cnt) {
        float t = ss + g_s_all[jj.y];
        t = (t >= 0.f) ? t : 0.01f * t;
        s1 = expf(t);
    }

    unsigned long long k0 = ((unsigned long long)fkey(s0) << 6) | (unsigned)(63 - p0);
    unsigned long long k1 = ((unsigned long long)fkey(s1) << 6) | (unsigned)(63 - p1);

    float vals[KSEL];
    int   sel[KSEL];
#pragma unroll
    for (int t = 0; t < KSEL; t++) {
        unsigned long long best = (k0 > k1) ? k0 : k1;
#pragma unroll
        for (int off = 16; off; off >>= 1) {
            unsigned long long o = __shfl_xor_sync(0xffffffffu, best, off);
            if (o > best) best = o;
        }
        int pos = 63 - (int)(best & 63ull);          // uniform across warp
        vals[t] = funkey((unsigned)(best >> 6));
        // Fetch the neighbor id from the lane that owns `pos` (no mem traffic).
        int cand = (pos & 1) ? jj.y : jj.x;          // selector uniform
        sel[t] = __shfl_sync(0xffffffffu, cand, pos >> 1);
        if (pos == p0) k0 = 0ull;                    // knock out the winner
        if (pos == p1) k1 = 0ull;
    }

    if (lane == 0) {
        size_t vb = (size_t)node * KSEL;
        out[vb + 0] = vals[0];
        out[vb + 1] = vals[1];
        out[vb + 2] = vals[2];
        float* osel = out + (size_t)N * KSEL;        // selected, cast to f32 (exact < 2^24)
        osel[vb + 0] = (float)sel[0];
        osel[vb + 1] = (float)sel[1];
        osel[vb + 2] = (float)sel[2];
    }
}

extern "C" void kernel_launch(void* const* d_in, const int* in_sizes, int n_in,
                              void* d_out, int out_size) {
    // metadata order: node_features, neighbors, neighbor_counts, W, b
    const float* x         = (const float*)d_in[0];
    const int*   neighbors = (const int*)d_in[1];   // jax x64-disabled -> int32
    const int*   counts    = (const int*)d_in[2];
    const float* W         = (const float*)d_in[3];
    const float* bias      = (const float*)d_in[4];

    int N = in_sizes[0] / DFEAT;
    if (N > NMAX) N = NMAX;

    int blocks = (N + 7) / 8;   // 8 warps (nodes) per 256-thread block
    score_kernel<<<blocks, 256>>>(x, W, bias, N);
    topk_kernel<<<blocks, 256>>>(neighbors, counts, (float*)d_out, N);
}

// round 2
// speedup vs baseline: 1.2051x; 1.2051x over previous
#include <cuda_runtime.h>
#include <math.h>

#define NMAX 200000
#define DFEAT 256
#define MNB   64
#define KSEL  3
#define NODES_PER_WARP 8

// Scratch (allocation-free): per-node projections.
__device__ float g_s_self[NMAX];
__device__ float g_s_all[NMAX];

// ---------------------------------------------------------------------------
// Kernel 1: one warp handles NODES_PER_WARP consecutive nodes. W is hoisted
// into registers (16 floats/lane) once; per node: 2 float4 loads per lane,
// dual FMA chains, combined shfl reduction.
// ---------------------------------------------------------------------------
__global__ void __launch_bounds__(256) score_kernel(const float* __restrict__ x,
                                                    const float* __restrict__ W,
                                                    const float* __restrict__ bias,
                                                    int N) {
    int warp = (blockIdx.x * 256 + threadIdx.x) >> 5;
    int lane = threadIdx.x & 31;
    int node0 = warp * NODES_PER_WARP;
    if (node0 >= N) return;

    const float4* wa4 = (const float4*)(W);          // W[0:256]
    const float4* wb4 = (const float4*)(W + DFEAT);  // W[256:512]
    float4 a0 = __ldg(wa4 + lane), a1 = __ldg(wa4 + lane + 32);
    float4 b0 = __ldg(wb4 + lane), b1 = __ldg(wb4 + lane + 32);
    float bb = bias[0];

    int nEnd = node0 + NODES_PER_WARP;
    if (nEnd > N) nEnd = N;
    for (int node = node0; node < nEnd; node++) {
        const float4* xr = (const float4*)(x + (size_t)node * DFEAT);
        float4 x0 = __ldg(xr + lane);
        float4 x1 = __ldg(xr + lane + 32);

        float sa, sb;
        sa  = x0.x * a0.x; sa = fmaf(x0.y, a0.y, sa);
        sa  = fmaf(x0.z, a0.z, sa); sa = fmaf(x0.w, a0.w, sa);
        sa  = fmaf(x1.x, a1.x, sa); sa = fmaf(x1.y, a1.y, sa);
        sa  = fmaf(x1.z, a1.z, sa); sa = fmaf(x1.w, a1.w, sa);
        sb  = x0.x * b0.x; sb = fmaf(x0.y, b0.y, sb);
        sb  = fmaf(x0.z, b0.z, sb); sb = fmaf(x0.w, b0.w, sb);
        sb  = fmaf(x1.x, b1.x, sb); sb = fmaf(x1.y, b1.y, sb);
        sb  = fmaf(x1.z, b1.z, sb); sb = fmaf(x1.w, b1.w, sb);
#pragma unroll
        for (int off = 16; off; off >>= 1) {
            sa += __shfl_xor_sync(0xffffffffu, sa, off);
            sb += __shfl_xor_sync(0xffffffffu, sb, off);
        }
        if (lane == 0) {
            g_s_self[node] = sa + bb;
            g_s_all[node]  = sb;
        }
    }
}

// Order-preserving float<->uint mapping (total order on floats).
__device__ __forceinline__ unsigned fkey(float f) {
    unsigned u = __float_as_uint(f);
    return (u & 0x80000000u) ? ~u : (u | 0x80000000u);
}
__device__ __forceinline__ float funkey(unsigned u) {
    unsigned b = (u & 0x80000000u) ? (u & 0x7fffffffu) : ~u;
    return __uint_as_float(b);
}

// ---------------------------------------------------------------------------
// Kernel 2: one warp per node. Monotonicity: exp(leaky_relu(ss + s_nb)) is
// strictly increasing in s_nb, so rank on 32-bit keys of s_all[j] directly,
// ties broken toward LOWER column (matching jax top_k for equal scores).
// Hardware REDUX (reduce_max/reduce_min) instead of 64-bit shfl trees.
// exp/leaky computed only for the 3 winners at the end.
// ---------------------------------------------------------------------------
__global__ void __launch_bounds__(256) topk_kernel(const int* __restrict__ neighbors,
                                                   const int* __restrict__ counts,
                                                   float* __restrict__ out,
                                                   int N) {
    int node = (blockIdx.x * 256 + threadIdx.x) >> 5;
    int lane = threadIdx.x & 31;
    if (node >= N) return;

    int cnt = counts[node];

    const int2* nb = (const int2*)(neighbors + (size_t)node * MNB);
    int2 jj = __ldg(nb + lane);            // positions 2*lane, 2*lane+1
    int p0 = 2 * lane, p1 = 2 * lane + 1;

    // key 0 < fkey(any float): marks invalid. cnt >= K guaranteed, so the
    // top-3 are always valid entries.
    unsigned k0 = (p0 < cnt) ? fkey(g_s_all[jj.x]) : 0u;
    unsigned k1 = (p1 < cnt) ? fkey(g_s_all[jj.y]) : 0u;

    unsigned winkey[KSEL];
    int      sel[KSEL];
#pragma unroll
    for (int t = 0; t < KSEL; t++) {
        unsigned maxk = __reduce_max_sync(0xffffffffu, (k0 > k1) ? k0 : k1);
        unsigned pc = 64;
        if (k0 == maxk)      pc = (unsigned)p0;
        else if (k1 == maxk) pc = (unsigned)p1;
        unsigned pos = __reduce_min_sync(0xffffffffu, pc);
        winkey[t] = maxk;
        int cand = (pos & 1u) ? jj.y : jj.x;             // pos uniform
        sel[t] = __shfl_sync(0xffffffffu, cand, pos >> 1);
        if (pos == (unsigned)p0) k0 = 0u;                // knock out winner
        if (pos == (unsigned)p1) k1 = 0u;
    }

    if (lane == 0) {
        float ss = g_s_self[node];
        size_t vb = (size_t)node * KSEL;
        float* osel = out + (size_t)N * KSEL;
#pragma unroll
        for (int t = 0; t < KSEL; t++) {
            float v = ss + funkey(winkey[t]);
            v = (v >= 0.f) ? v : 0.01f * v;              // leaky_relu (jax default)
            out[vb + t]  = expf(v);
            osel[vb + t] = (float)sel[t];                // exact: ids < 2^24
        }
    }
}

extern "C" void kernel_launch(void* const* d_in, const int* in_sizes, int n_in,
                              void* d_out, int out_size) {
    // metadata order: node_features, neighbors, neighbor_counts, W, b
    const float* x         = (const float*)d_in[0];
    const int*   neighbors = (const int*)d_in[1];
    const int*   counts    = (const int*)d_in[2];
    const float* W         = (const float*)d_in[3];
    const float* bias      = (const float*)d_in[4];

    int N = in_sizes[0] / DFEAT;
    if (N > NMAX) N = NMAX;

    int warps1  = (N + NODES_PER_WARP - 1) / NODES_PER_WARP;
    int blocks1 = (warps1 + 7) / 8;
    score_kernel<<<blocks1, 256>>>(x, W, bias, N);

    int blocks2 = (N + 7) / 8;   // 8 warps (nodes) per 256-thread block
    topk_kernel<<<blocks2, 256>>>(neighbors, counts, (float*)d_out, N);
}